// round 6
// baseline (speedup 1.0000x reference)
#include <cuda_runtime.h>
#include <cuda_bf16.h>
#include <cstdint>

// ---------------------------------------------------------------------------
// ViT encoder block. GEMMs: mma.sync bf16 2-term split, 256x128 CTA tile,
// 64x64 warp tile (6:1 MMA:ldmatrix), cp.async 2-stage. Merged QKV.
// Attention + LayerNorm fp32 SIMT.
// ---------------------------------------------------------------------------

#define NTOK   16384
#define EMB    768
#define FFND   3072
#define HEADS  12
#define DK     64
#define SEQ    512
#define BATCH  32
#define QKVN   2304

// ----- fp32 scratch -----
__device__ __align__(128) float g_qkv[NTOK * QKVN];
__device__ __align__(128) float g_tmp[NTOK * EMB];
__device__ __align__(128) float g_x1 [NTOK * EMB];

// ----- bf16 split scratch -----
__device__ __align__(128) __nv_bfloat16 g_ah[NTOK * EMB];
__device__ __align__(128) __nv_bfloat16 g_al[NTOK * EMB];
__device__ __align__(128) __nv_bfloat16 g_ch[NTOK * EMB];
__device__ __align__(128) __nv_bfloat16 g_cl[NTOK * EMB];
__device__ __align__(128) __nv_bfloat16 g_fh[NTOK * FFND];
__device__ __align__(128) __nv_bfloat16 g_fl[NTOK * FFND];
#define WTOT 7077888
__device__ __align__(128) __nv_bfloat16 g_wh[WTOT];
__device__ __align__(128) __nv_bfloat16 g_wl[WTOT];

// ===========================================================================
// helpers
// ===========================================================================
__device__ __forceinline__ void ldsm4(uint32_t* r, const void* p) {
    uint32_t a = (uint32_t)__cvta_generic_to_shared(p);
    asm volatile("ldmatrix.sync.aligned.m8n8.x4.shared.b16 {%0,%1,%2,%3}, [%4];"
                 : "=r"(r[0]), "=r"(r[1]), "=r"(r[2]), "=r"(r[3]) : "r"(a));
}
__device__ __forceinline__ void ldsm4t(uint32_t* r, const void* p) {
    uint32_t a = (uint32_t)__cvta_generic_to_shared(p);
    asm volatile("ldmatrix.sync.aligned.m8n8.x4.trans.shared.b16 {%0,%1,%2,%3}, [%4];"
                 : "=r"(r[0]), "=r"(r[1]), "=r"(r[2]), "=r"(r[3]) : "r"(a));
}
__device__ __forceinline__ void mma16816(float* c, const uint32_t* a, const uint32_t* b) {
    asm volatile("mma.sync.aligned.m16n8k16.row.col.f32.bf16.bf16.f32 "
                 "{%0,%1,%2,%3}, {%4,%5,%6,%7}, {%8,%9}, {%0,%1,%2,%3};"
                 : "+f"(c[0]), "+f"(c[1]), "+f"(c[2]), "+f"(c[3])
                 : "r"(a[0]), "r"(a[1]), "r"(a[2]), "r"(a[3]), "r"(b[0]), "r"(b[1]));
}
__device__ __forceinline__ void cpa16(uint32_t dst, const void* src) {
    asm volatile("cp.async.cg.shared.global [%0], [%1], 16;" :: "r"(dst), "l"(src));
}
__device__ __forceinline__ void cpa_commit() {
    asm volatile("cp.async.commit_group;" ::: "memory");
}
__device__ __forceinline__ void cpa_wait0() {
    asm volatile("cp.async.wait_group 0;" ::: "memory");
}

// ===========================================================================
// split: fp32 -> bf16 hi + lo (contiguous, for activations)
// ===========================================================================
__global__ __launch_bounds__(256) void split_kernel(
    const float* __restrict__ in, __nv_bfloat16* __restrict__ h,
    __nv_bfloat16* __restrict__ l, int n)
{
    int i = (blockIdx.x * 256 + threadIdx.x) * 4;
    if (i >= n) return;
    float4 v = *(const float4*)(in + i);
    __nv_bfloat16 h0 = __float2bfloat16(v.x);
    __nv_bfloat16 h1 = __float2bfloat16(v.y);
    __nv_bfloat16 h2 = __float2bfloat16(v.z);
    __nv_bfloat16 h3 = __float2bfloat16(v.w);
    __nv_bfloat162 a; a.x = h0; a.y = h1;
    __nv_bfloat162 b; b.x = h2; b.y = h3;
    __nv_bfloat162 c; c.x = __float2bfloat16(v.x - __bfloat162float(h0));
    c.y = __float2bfloat16(v.y - __bfloat162float(h1));
    __nv_bfloat162 d; d.x = __float2bfloat16(v.z - __bfloat162float(h2));
    d.y = __float2bfloat16(v.w - __bfloat162float(h3));
    *reinterpret_cast<__nv_bfloat162*>(h + i)     = a;
    *reinterpret_cast<__nv_bfloat162*>(h + i + 2) = b;
    *reinterpret_cast<__nv_bfloat162*>(l + i)     = c;
    *reinterpret_cast<__nv_bfloat162*>(l + i + 2) = d;
}

// ===========================================================================
// splitw: W[K,N] fp32 -> merged hi/lo at column offset `off`, width Ntot
// ===========================================================================
__global__ __launch_bounds__(256) void splitw_kernel(
    const float* __restrict__ W, __nv_bfloat16* __restrict__ h,
    __nv_bfloat16* __restrict__ l, int N, int Ntot, int off, int total)
{
    int i = (blockIdx.x * 256 + threadIdx.x) * 4;
    if (i >= total) return;
    int k = i / N, n = i - k * N;
    size_t o = (size_t)k * Ntot + off + n;
    float4 v = *(const float4*)(W + i);
    __nv_bfloat16 h0 = __float2bfloat16(v.x);
    __nv_bfloat16 h1 = __float2bfloat16(v.y);
    __nv_bfloat16 h2 = __float2bfloat16(v.z);
    __nv_bfloat16 h3 = __float2bfloat16(v.w);
    __nv_bfloat162 a; a.x = h0; a.y = h1;
    __nv_bfloat162 b; b.x = h2; b.y = h3;
    __nv_bfloat162 c; c.x = __float2bfloat16(v.x - __bfloat162float(h0));
    c.y = __float2bfloat16(v.y - __bfloat162float(h1));
    __nv_bfloat162 d; d.x = __float2bfloat16(v.z - __bfloat162float(h2));
    d.y = __float2bfloat16(v.w - __bfloat162float(h3));
    *reinterpret_cast<__nv_bfloat162*>(h + o)     = a;
    *reinterpret_cast<__nv_bfloat162*>(h + o + 2) = b;
    *reinterpret_cast<__nv_bfloat162*>(l + o)     = c;
    *reinterpret_cast<__nv_bfloat162*>(l + o + 2) = d;
}

// ===========================================================================
// GEMM: C[M,N] = A[M,K] @ B[K,N]; A/B bf16 hi/lo.
// CTA tile 256x128, BK=16, 256 threads (4x2 warps, 64x64 per warp).
// cp.async 2-stage double buffer; one wait+barrier per k-iter.
// EPI: 0 = fp32 C; 1 = +bias fp32 C; 3 = +bias+relu -> bf16 split Ch/Cl
// ===========================================================================
#define ASTR 24    // A smem row stride (elems)
#define BSTR 136   // B smem row stride (elems)
// per-stage byte layout
#define ST_AH 0
#define ST_AL 12288              // 256*24*2
#define ST_BH 24576
#define ST_BL 28928              // +16*136*2
#define ST_SZ 33280
#define GSMEM (2 * ST_SZ)        // 66560

template <int EPI>
__global__ __launch_bounds__(256, 1) void tgemm(
    const __nv_bfloat16* __restrict__ Ah, const __nv_bfloat16* __restrict__ Al,
    const __nv_bfloat16* __restrict__ Bh, const __nv_bfloat16* __restrict__ Bl,
    const float* __restrict__ bias, float* __restrict__ C,
    __nv_bfloat16* __restrict__ Ch, __nv_bfloat16* __restrict__ Cl,
    int M, int N, int K)
{
    extern __shared__ char smem[];
    const uint32_t sb = (uint32_t)__cvta_generic_to_shared(smem);

    const int tid  = threadIdx.x;
    const int lane = tid & 31;
    const int w    = tid >> 5;
    const int wm   = w & 3;     // 4 m-groups of 64 rows
    const int wn   = w >> 2;    // 2 n-groups of 64 cols
    const int bm   = blockIdx.y * 256;
    const int bn   = blockIdx.x * 128;

    // loaders: A -> thread = one row (tid), two 16B chunks per matrix
    //          B -> thread = one (krow, 8-col group) chunk per matrix
    const int br = tid >> 4;          // 0..15
    const int bc = (tid & 15) * 8;    // 0..120

    const __nv_bfloat16* gAh = Ah + (size_t)(bm + tid) * K;
    const __nv_bfloat16* gAl = Al + (size_t)(bm + tid) * K;
    const __nv_bfloat16* gBh = Bh + (size_t)br * N + bn + bc;
    const __nv_bfloat16* gBl = Bl + (size_t)br * N + bn + bc;

    const uint32_t dA = sb + (uint32_t)(tid * ASTR) * 2;
    const uint32_t dB = sb + (uint32_t)(br * BSTR + bc) * 2;

    auto load_stage = [&](int s, int kt) {
        const uint32_t o = (uint32_t)s * ST_SZ;
        const int k0 = kt * 16;
        cpa16(dA + o + ST_AH,      gAh + k0);
        cpa16(dA + o + ST_AH + 16, gAh + k0 + 8);
        cpa16(dA + o + ST_AL,      gAl + k0);
        cpa16(dA + o + ST_AL + 16, gAl + k0 + 8);
        cpa16(dB + o + ST_BH,      gBh + (size_t)k0 * N);
        cpa16(dB + o + ST_BL,      gBl + (size_t)k0 * N);
    };

    // ldmatrix element offsets within a stage
    int a_off[4];
#pragma unroll
    for (int mi = 0; mi < 4; mi++) {
        int row = wm * 64 + mi * 16 + (lane & 15);
        int col = (lane >> 4) * 8;
        a_off[mi] = row * ASTR + col;
    }
    int b_off[4];
    {
        int krow = lane & 15;
#pragma unroll
        for (int p = 0; p < 4; p++) {
            int col = wn * 64 + (p * 2 + (lane >> 4)) * 8;
            b_off[p] = krow * BSTR + col;
        }
    }

    float c[4][8][4];
#pragma unroll
    for (int mi = 0; mi < 4; mi++)
#pragma unroll
        for (int ni = 0; ni < 8; ni++)
#pragma unroll
            for (int e = 0; e < 4; e++) c[mi][ni][e] = 0.f;

    const int nk = K >> 4;

    // prologue
    load_stage(0, 0);
    cpa_commit();

    for (int kt = 0; kt < nk; kt++) {
        const int buf = kt & 1;
        cpa_wait0();
        __syncthreads();
        if (kt + 1 < nk) {
            load_stage(buf ^ 1, kt + 1);
            cpa_commit();
        }

        const char* stg = smem + (uint32_t)buf * ST_SZ;

        uint32_t fah[4][4], fal[4][4], fb[8][2];
#pragma unroll
        for (int mi = 0; mi < 4; mi++) {
            ldsm4(fah[mi], stg + ST_AH + a_off[mi] * 2);
            ldsm4(fal[mi], stg + ST_AL + a_off[mi] * 2);
        }
        // B hi
#pragma unroll
        for (int p = 0; p < 4; p++) {
            uint32_t r[4];
            ldsm4t(r, stg + ST_BH + b_off[p] * 2);
            fb[p * 2][0] = r[0]; fb[p * 2][1] = r[1];
            fb[p * 2 + 1][0] = r[2]; fb[p * 2 + 1][1] = r[3];
        }
#pragma unroll
        for (int mi = 0; mi < 4; mi++)
#pragma unroll
            for (int ni = 0; ni < 8; ni++) mma16816(c[mi][ni], fah[mi], fb[ni]);  // hh
#pragma unroll
        for (int mi = 0; mi < 4; mi++)
#pragma unroll
            for (int ni = 0; ni < 8; ni++) mma16816(c[mi][ni], fal[mi], fb[ni]);  // lh
        // B lo (reuse fb regs)
#pragma unroll
        for (int p = 0; p < 4; p++) {
            uint32_t r[4];
            ldsm4t(r, stg + ST_BL + b_off[p] * 2);
            fb[p * 2][0] = r[0]; fb[p * 2][1] = r[1];
            fb[p * 2 + 1][0] = r[2]; fb[p * 2 + 1][1] = r[3];
        }
#pragma unroll
        for (int mi = 0; mi < 4; mi++)
#pragma unroll
            for (int ni = 0; ni < 8; ni++) mma16816(c[mi][ni], fah[mi], fb[ni]);  // hl
    }

    // epilogue
    const int er = lane >> 2;
    const int ec = (lane & 3) * 2;
#pragma unroll
    for (int mi = 0; mi < 4; mi++) {
#pragma unroll
        for (int ni = 0; ni < 8; ni++) {
            int r0 = bm + wm * 64 + mi * 16 + er;
            int cc = bn + wn * 64 + ni * 8 + ec;
            float v0 = c[mi][ni][0], v1 = c[mi][ni][1];
            float v2 = c[mi][ni][2], v3 = c[mi][ni][3];
            if (EPI >= 1) {
                float bi0 = bias[cc], bi1 = bias[cc + 1];
                v0 += bi0; v1 += bi1; v2 += bi0; v3 += bi1;
            }
            if (EPI == 3) {
                v0 = fmaxf(v0, 0.f); v1 = fmaxf(v1, 0.f);
                v2 = fmaxf(v2, 0.f); v3 = fmaxf(v3, 0.f);
                __nv_bfloat16 h0 = __float2bfloat16(v0);
                __nv_bfloat16 h1 = __float2bfloat16(v1);
                __nv_bfloat16 h2 = __float2bfloat16(v2);
                __nv_bfloat16 h3 = __float2bfloat16(v3);
                __nv_bfloat162 hp0; hp0.x = h0; hp0.y = h1;
                __nv_bfloat162 hp1; hp1.x = h2; hp1.y = h3;
                __nv_bfloat162 lp0;
                lp0.x = __float2bfloat16(v0 - __bfloat162float(h0));
                lp0.y = __float2bfloat16(v1 - __bfloat162float(h1));
                __nv_bfloat162 lp1;
                lp1.x = __float2bfloat16(v2 - __bfloat162float(h2));
                lp1.y = __float2bfloat16(v3 - __bfloat162float(h3));
                *reinterpret_cast<__nv_bfloat162*>(&Ch[(size_t)r0 * N + cc])       = hp0;
                *reinterpret_cast<__nv_bfloat162*>(&Cl[(size_t)r0 * N + cc])       = lp0;
                *reinterpret_cast<__nv_bfloat162*>(&Ch[(size_t)(r0 + 8) * N + cc]) = hp1;
                *reinterpret_cast<__nv_bfloat162*>(&Cl[(size_t)(r0 + 8) * N + cc]) = lp1;
            } else {
                *(float2*)&C[(size_t)r0 * N + cc]       = make_float2(v0, v1);
                *(float2*)&C[(size_t)(r0 + 8) * N + cc] = make_float2(v2, v3);
            }
        }
    }
}

// ===========================================================================
// Attention (fp32 SIMT) reading fused QKV [NTOK, 2304]; ctx -> bf16 split.
// ===========================================================================
__global__ __launch_bounds__(256) void attn_kernel(
    const float* __restrict__ QKV,
    __nv_bfloat16* __restrict__ Oh, __nv_bfloat16* __restrict__ Ol)
{
    extern __shared__ float sm[];
    float* sQ  = sm;
    float* sK  = sQ + 2048;
    float* sKt = sK + 4096;
    float* sS  = sKt + 4352;

    const int qt  = blockIdx.x;
    const int h   = blockIdx.y;
    const int b   = blockIdx.z;
    const int tid = threadIdx.x;
    const size_t base = (size_t)b * SEQ * QKVN + h * DK;

    for (int i = tid; i < 512; i += 256) {
        int r = i >> 4, cx = (i & 15) * 4;
        *(float4*)&sQ[r * 64 + cx] =
            *(const float4*)&QKV[base + (size_t)(qt * 32 + r) * QKVN + cx];
    }

    const int gq  = tid >> 4;
    const int gk  = tid & 15;
    const int qi0 = gq * 2;
    const int kj0 = gk * 4;

    for (int kt = 0; kt < 8; kt++) {
        __syncthreads();
        for (int i = tid; i < 1024; i += 256) {
            int r = i >> 4, cx = (i & 15) * 4;
            *(float4*)&sK[r * 64 + cx] =
                *(const float4*)&QKV[base + 768 + (size_t)(kt * 64 + r) * QKVN + cx];
        }
        __syncthreads();
        for (int i = tid; i < 4096; i += 256) {
            int d = i & 63, r = i >> 6;
            sKt[d * 68 + r] = sK[r * 64 + d];
        }
        __syncthreads();

        float acc[2][4] = {{0.f,0.f,0.f,0.f},{0.f,0.f,0.f,0.f}};
#pragma unroll 8
        for (int d = 0; d < 64; d++) {
            float q0 = sQ[qi0 * 64 + d];
            float q1 = sQ[qi0 * 64 + 64 + d];
            float4 kv = *(float4*)&sKt[d * 68 + kj0];
            acc[0][0] += q0 * kv.x; acc[0][1] += q0 * kv.y;
            acc[0][2] += q0 * kv.z; acc[0][3] += q0 * kv.w;
            acc[1][0] += q1 * kv.x; acc[1][1] += q1 * kv.y;
            acc[1][2] += q1 * kv.z; acc[1][3] += q1 * kv.w;
        }
#pragma unroll
        for (int i = 0; i < 2; i++)
#pragma unroll
            for (int j = 0; j < 4; j++)
                sS[(qi0 + i) * 512 + kt * 64 + kj0 + j] = acc[i][j] * 0.125f;
    }
    __syncthreads();

    {
        const int wid = tid >> 5, lanei = tid & 31;
        for (int r = wid * 4; r < wid * 4 + 4; r++) {
            float* srow = sS + r * 512;
            float m = -1e30f;
            for (int cx = lanei; cx < 512; cx += 32) m = fmaxf(m, srow[cx]);
#pragma unroll
            for (int o = 16; o > 0; o >>= 1)
                m = fmaxf(m, __shfl_xor_sync(0xffffffffu, m, o));
            float s = 0.f;
            for (int cx = lanei; cx < 512; cx += 32) {
                float e = __expf(srow[cx] - m);
                srow[cx] = e;
                s += e;
            }
#pragma unroll
            for (int o = 16; o > 0; o >>= 1)
                s += __shfl_xor_sync(0xffffffffu, s, o);
            float inv = 1.0f / s;
            for (int cx = lanei; cx < 512; cx += 32) srow[cx] *= inv;
        }
    }

    const int d0 = gk * 4;
    float o_[2][4] = {{0.f,0.f,0.f,0.f},{0.f,0.f,0.f,0.f}};
    for (int kt = 0; kt < 8; kt++) {
        __syncthreads();
        for (int i = tid; i < 1024; i += 256) {
            int r = i >> 4, cx = (i & 15) * 4;
            *(float4*)&sK[r * 64 + cx] =
                *(const float4*)&QKV[base + 1536 + (size_t)(kt * 64 + r) * QKVN + cx];
        }
        __syncthreads();
#pragma unroll 4
        for (int k = 0; k < 64; k++) {
            float s0 = sS[qi0 * 512 + kt * 64 + k];
            float s1 = sS[qi0 * 512 + 512 + kt * 64 + k];
            float4 vv = *(float4*)&sK[k * 64 + d0];
            o_[0][0] += s0 * vv.x; o_[0][1] += s0 * vv.y;
            o_[0][2] += s0 * vv.z; o_[0][3] += s0 * vv.w;
            o_[1][0] += s1 * vv.x; o_[1][1] += s1 * vv.y;
            o_[1][2] += s1 * vv.z; o_[1][3] += s1 * vv.w;
        }
    }

#pragma unroll
    for (int i = 0; i < 2; i++) {
        size_t idx = ((size_t)b * SEQ + qt * 32 + qi0 + i) * EMB + h * DK + d0;
        __nv_bfloat16 h0 = __float2bfloat16(o_[i][0]);
        __nv_bfloat16 h1 = __float2bfloat16(o_[i][1]);
        __nv_bfloat16 h2 = __float2bfloat16(o_[i][2]);
        __nv_bfloat16 h3 = __float2bfloat16(o_[i][3]);
        __nv_bfloat162 hp0; hp0.x = h0; hp0.y = h1;
        __nv_bfloat162 hp1; hp1.x = h2; hp1.y = h3;
        __nv_bfloat162 lp0;
        lp0.x = __float2bfloat16(o_[i][0] - __bfloat162float(h0));
        lp0.y = __float2bfloat16(o_[i][1] - __bfloat162float(h1));
        __nv_bfloat162 lp1;
        lp1.x = __float2bfloat16(o_[i][2] - __bfloat162float(h2));
        lp1.y = __float2bfloat16(o_[i][3] - __bfloat162float(h3));
        *reinterpret_cast<__nv_bfloat162*>(&Oh[idx])     = hp0;
        *reinterpret_cast<__nv_bfloat162*>(&Oh[idx + 2]) = hp1;
        *reinterpret_cast<__nv_bfloat162*>(&Ol[idx])     = lp0;
        *reinterpret_cast<__nv_bfloat162*>(&Ol[idx + 2]) = lp1;
    }
}

// ===========================================================================
// Fused residual + LayerNorm (+ optional bf16 split out)
// ===========================================================================
__global__ __launch_bounds__(256) void add_ln_kernel(
    const float* __restrict__ x, const float* __restrict__ r,
    const float* __restrict__ gamma, const float* __restrict__ beta,
    float* __restrict__ out,
    __nv_bfloat16* __restrict__ oh, __nv_bfloat16* __restrict__ ol)
{
    const int row = blockIdx.x;
    const int tid = threadIdx.x;
    const float* xr = x + (size_t)row * EMB;
    const float* rr = r + (size_t)row * EMB;

    float v[3];
    float s = 0.f;
#pragma unroll
    for (int i = 0; i < 3; i++) {
        int cx = tid + i * 256;
        float t = xr[cx] + rr[cx];
        v[i] = t;
        s += t;
    }

    __shared__ float red[8];
    const int wid = tid >> 5, lane = tid & 31;
#pragma unroll
    for (int o = 16; o > 0; o >>= 1) s += __shfl_xor_sync(0xffffffffu, s, o);
    if (lane == 0) red[wid] = s;
    __syncthreads();
    if (tid == 0) {
        float t = 0.f;
#pragma unroll
        for (int i = 0; i < 8; i++) t += red[i];
        red[0] = t;
    }
    __syncthreads();
    const float mean = red[0] * (1.0f / 768.0f);

    float s2 = 0.f;
#pragma unroll
    for (int i = 0; i < 3; i++) {
        float d = v[i] - mean;
        s2 += d * d;
    }
#pragma unroll
    for (int o = 16; o > 0; o >>= 1) s2 += __shfl_xor_sync(0xffffffffu, s2, o);
    __syncthreads();
    if (lane == 0) red[wid] = s2;
    __syncthreads();
    if (tid == 0) {
        float t = 0.f;
#pragma unroll
        for (int i = 0; i < 8; i++) t += red[i];
        red[0] = t;
    }
    __syncthreads();
    const float var  = red[0] * (1.0f / 768.0f);
    const float rstd = rsqrtf(var + 1e-5f);

#pragma unroll
    for (int i = 0; i < 3; i++) {
        int cx = tid + i * 256;
        float o = (v[i] - mean) * rstd * gamma[cx] + beta[cx];
        size_t idx = (size_t)row * EMB + cx;
        out[idx] = o;
        if (oh) {
            __nv_bfloat16 hh = __float2bfloat16(o);
            oh[idx] = hh;
            ol[idx] = __float2bfloat16(o - __bfloat162float(hh));
        }
    }
}

// ===========================================================================
// Launch
// ===========================================================================
extern "C" void kernel_launch(void* const* d_in, const int* in_sizes, int n_in,
                              void* d_out, int out_size)
{
    (void)in_sizes; (void)n_in; (void)out_size;

    const float* x   = (const float*)d_in[0];
    const float* Wq  = (const float*)d_in[1];
    const float* Wk  = (const float*)d_in[2];
    const float* Wv  = (const float*)d_in[3];
    const float* Wo  = (const float*)d_in[4];
    const float* W1  = (const float*)d_in[5];
    const float* b1  = (const float*)d_in[6];
    const float* W2  = (const float*)d_in[7];
    const float* b2  = (const float*)d_in[8];
    const float* g1  = (const float*)d_in[9];
    const float* be1 = (const float*)d_in[10];
    const float* g2  = (const float*)d_in[11];
    const float* be2 = (const float*)d_in[12];
    float* out = (float*)d_out;

    float *qkv, *tmp, *x1;
    __nv_bfloat16 *ah, *al, *ch, *cl, *fh, *fl, *wh, *wl;
    cudaGetSymbolAddress((void**)&qkv, g_qkv);
    cudaGetSymbolAddress((void**)&tmp, g_tmp);
    cudaGetSymbolAddress((void**)&x1,  g_x1);
    cudaGetSymbolAddress((void**)&ah,  g_ah);
    cudaGetSymbolAddress((void**)&al,  g_al);
    cudaGetSymbolAddress((void**)&ch,  g_ch);
    cudaGetSymbolAddress((void**)&cl,  g_cl);
    cudaGetSymbolAddress((void**)&fh,  g_fh);
    cudaGetSymbolAddress((void**)&fl,  g_fl);
    cudaGetSymbolAddress((void**)&wh,  g_wh);
    cudaGetSymbolAddress((void**)&wl,  g_wl);

    const int ATTN_SMEM = (2048 + 4096 + 64 * 68 + 16384) * 4;
    cudaFuncSetAttribute(attn_kernel,
                         cudaFuncAttributeMaxDynamicSharedMemorySize, ATTN_SMEM);
    cudaFuncSetAttribute(tgemm<0>,
                         cudaFuncAttributeMaxDynamicSharedMemorySize, GSMEM);
    cudaFuncSetAttribute(tgemm<1>,
                         cudaFuncAttributeMaxDynamicSharedMemorySize, GSMEM);
    cudaFuncSetAttribute(tgemm<3>,
                         cudaFuncAttributeMaxDynamicSharedMemorySize, GSMEM);

    const size_t EE = (size_t)EMB * EMB;
    const size_t EF = (size_t)EMB * FFND;
    const size_t OQKV = 0, OO_ = 3 * EE, O1_ = 4 * EE, O2_ = 4 * EE + EF;

    dim3 blk(256);

    // activation split (x)
    split_kernel<<<NTOK * EMB / 1024, blk>>>(x, ah, al, NTOK * EMB);
    // weight splits; Wq/Wk/Wv scatter into merged [768,2304] buffer
    splitw_kernel<<<(int)(EE / 1024), blk>>>(Wq, wh + OQKV, wl + OQKV, EMB, QKVN, 0,    (int)EE);
    splitw_kernel<<<(int)(EE / 1024), blk>>>(Wk, wh + OQKV, wl + OQKV, EMB, QKVN, 768,  (int)EE);
    splitw_kernel<<<(int)(EE / 1024), blk>>>(Wv, wh + OQKV, wl + OQKV, EMB, QKVN, 1536, (int)EE);
    splitw_kernel<<<(int)(EE / 1024), blk>>>(Wo, wh + OO_,  wl + OO_,  EMB, EMB,  0,    (int)EE);
    splitw_kernel<<<(int)(EF / 1024), blk>>>(W1, wh + O1_,  wl + O1_,  FFND, FFND, 0,   (int)EF);
    splitw_kernel<<<(int)(EF / 1024), blk>>>(W2, wh + O2_,  wl + O2_,  EMB,  EMB,  0,   (int)EF);

    // fused QKV projection: [NTOK,768] @ [768,2304]
    tgemm<0><<<dim3(QKVN / 128, NTOK / 256), blk, GSMEM>>>(
        ah, al, wh + OQKV, wl + OQKV, nullptr, qkv, nullptr, nullptr, NTOK, QKVN, EMB);

    // attention -> ctx (bf16 split)
    attn_kernel<<<dim3(SEQ / 32, HEADS, BATCH), blk, ATTN_SMEM>>>(qkv, ch, cl);

    // output projection
    tgemm<0><<<dim3(EMB / 128, NTOK / 256), blk, GSMEM>>>(
        ch, cl, wh + OO_, wl + OO_, nullptr, tmp, nullptr, nullptr, NTOK, EMB, EMB);

    // residual + LN1 (emits x1 split into ah/al)
    add_ln_kernel<<<NTOK, blk>>>(x, tmp, g1, be1, x1, ah, al);

    // FFN
    tgemm<3><<<dim3(FFND / 128, NTOK / 256), blk, GSMEM>>>(
        ah, al, wh + O1_, wl + O1_, b1, nullptr, fh, fl, NTOK, FFND, EMB);
    tgemm<1><<<dim3(EMB / 128, NTOK / 256), blk, GSMEM>>>(
        fh, fl, wh + O2_, wl + O2_, b2, tmp, nullptr, nullptr, NTOK, EMB, FFND);

    // residual + LN2
    add_ln_kernel<<<NTOK, blk>>>(x1, tmp, g2, be2, out, nullptr, nullptr);
}

// round 7
// speedup vs baseline: 1.0894x; 1.0894x over previous
#include <cuda_runtime.h>
#include <cuda_bf16.h>
#include <cstdint>

// ---------------------------------------------------------------------------
// ViT encoder block. GEMMs: mma.sync bf16 2-term split, 256x128 CTA tile,
// 64x64 warp tile, REGISTER-PREFETCH double-buffered smem (proven feeding).
// Merged QKV. Attention + LayerNorm fp32 SIMT.
// ---------------------------------------------------------------------------

#define NTOK   16384
#define EMB    768
#define FFND   3072
#define HEADS  12
#define DK     64
#define SEQ    512
#define BATCH  32
#define QKVN   2304

// ----- fp32 scratch -----
__device__ __align__(128) float g_qkv[NTOK * QKVN];
__device__ __align__(128) float g_tmp[NTOK * EMB];
__device__ __align__(128) float g_x1 [NTOK * EMB];

// ----- bf16 split scratch -----
__device__ __align__(128) __nv_bfloat16 g_ah[NTOK * EMB];
__device__ __align__(128) __nv_bfloat16 g_al[NTOK * EMB];
__device__ __align__(128) __nv_bfloat16 g_ch[NTOK * EMB];
__device__ __align__(128) __nv_bfloat16 g_cl[NTOK * EMB];
__device__ __align__(128) __nv_bfloat16 g_fh[NTOK * FFND];
__device__ __align__(128) __nv_bfloat16 g_fl[NTOK * FFND];
#define WTOT 7077888
__device__ __align__(128) __nv_bfloat16 g_wh[WTOT];
__device__ __align__(128) __nv_bfloat16 g_wl[WTOT];

// ===========================================================================
// helpers
// ===========================================================================
__device__ __forceinline__ void ldsm4(uint32_t* r, const void* p) {
    uint32_t a = (uint32_t)__cvta_generic_to_shared(p);
    asm volatile("ldmatrix.sync.aligned.m8n8.x4.shared.b16 {%0,%1,%2,%3}, [%4];"
                 : "=r"(r[0]), "=r"(r[1]), "=r"(r[2]), "=r"(r[3]) : "r"(a));
}
__device__ __forceinline__ void ldsm4t(uint32_t* r, const void* p) {
    uint32_t a = (uint32_t)__cvta_generic_to_shared(p);
    asm volatile("ldmatrix.sync.aligned.m8n8.x4.trans.shared.b16 {%0,%1,%2,%3}, [%4];"
                 : "=r"(r[0]), "=r"(r[1]), "=r"(r[2]), "=r"(r[3]) : "r"(a));
}
__device__ __forceinline__ void mma16816(float* c, const uint32_t* a, const uint32_t* b) {
    asm volatile("mma.sync.aligned.m16n8k16.row.col.f32.bf16.bf16.f32 "
                 "{%0,%1,%2,%3}, {%4,%5,%6,%7}, {%8,%9}, {%0,%1,%2,%3};"
                 : "+f"(c[0]), "+f"(c[1]), "+f"(c[2]), "+f"(c[3])
                 : "r"(a[0]), "r"(a[1]), "r"(a[2]), "r"(a[3]), "r"(b[0]), "r"(b[1]));
}

// ===========================================================================
// split: fp32 -> bf16 hi + lo (contiguous, for activations)
// ===========================================================================
__global__ __launch_bounds__(256) void split_kernel(
    const float* __restrict__ in, __nv_bfloat16* __restrict__ h,
    __nv_bfloat16* __restrict__ l, int n)
{
    int i = (blockIdx.x * 256 + threadIdx.x) * 4;
    if (i >= n) return;
    float4 v = *(const float4*)(in + i);
    __nv_bfloat16 h0 = __float2bfloat16(v.x);
    __nv_bfloat16 h1 = __float2bfloat16(v.y);
    __nv_bfloat16 h2 = __float2bfloat16(v.z);
    __nv_bfloat16 h3 = __float2bfloat16(v.w);
    __nv_bfloat162 a; a.x = h0; a.y = h1;
    __nv_bfloat162 b; b.x = h2; b.y = h3;
    __nv_bfloat162 c; c.x = __float2bfloat16(v.x - __bfloat162float(h0));
    c.y = __float2bfloat16(v.y - __bfloat162float(h1));
    __nv_bfloat162 d; d.x = __float2bfloat16(v.z - __bfloat162float(h2));
    d.y = __float2bfloat16(v.w - __bfloat162float(h3));
    *reinterpret_cast<__nv_bfloat162*>(h + i)     = a;
    *reinterpret_cast<__nv_bfloat162*>(h + i + 2) = b;
    *reinterpret_cast<__nv_bfloat162*>(l + i)     = c;
    *reinterpret_cast<__nv_bfloat162*>(l + i + 2) = d;
}

// ===========================================================================
// splitw: W[K,N] fp32 -> merged hi/lo at column offset `off`, width Ntot
// ===========================================================================
__global__ __launch_bounds__(256) void splitw_kernel(
    const float* __restrict__ W, __nv_bfloat16* __restrict__ h,
    __nv_bfloat16* __restrict__ l, int N, int Ntot, int off, int total)
{
    int i = (blockIdx.x * 256 + threadIdx.x) * 4;
    if (i >= total) return;
    int k = i / N, n = i - k * N;
    size_t o = (size_t)k * Ntot + off + n;
    float4 v = *(const float4*)(W + i);
    __nv_bfloat16 h0 = __float2bfloat16(v.x);
    __nv_bfloat16 h1 = __float2bfloat16(v.y);
    __nv_bfloat16 h2 = __float2bfloat16(v.z);
    __nv_bfloat16 h3 = __float2bfloat16(v.w);
    __nv_bfloat162 a; a.x = h0; a.y = h1;
    __nv_bfloat162 b; b.x = h2; b.y = h3;
    __nv_bfloat162 c; c.x = __float2bfloat16(v.x - __bfloat162float(h0));
    c.y = __float2bfloat16(v.y - __bfloat162float(h1));
    __nv_bfloat162 d; d.x = __float2bfloat16(v.z - __bfloat162float(h2));
    d.y = __float2bfloat16(v.w - __bfloat162float(h3));
    *reinterpret_cast<__nv_bfloat162*>(h + o)     = a;
    *reinterpret_cast<__nv_bfloat162*>(h + o + 2) = b;
    *reinterpret_cast<__nv_bfloat162*>(l + o)     = c;
    *reinterpret_cast<__nv_bfloat162*>(l + o + 2) = d;
}

// ===========================================================================
// GEMM: C[M,N] = A[M,K] @ B[K,N]; A/B bf16 hi/lo.
// CTA 256x128, BK=16, 256 threads (4x2 warps, 64x64 per warp).
// Register prefetch + double-buffered smem, one sync per k-iter.
// EPI: 0 = fp32 C; 1 = +bias fp32 C; 3 = +bias+relu -> bf16 split Ch/Cl
// ===========================================================================
#define ASTR 24    // A smem row stride (elems)
#define BSTR 136   // B smem row stride (elems)
// per-stage byte layout (dynamic smem)
#define ST_AH 0
#define ST_AL 12288              // 256*24*2
#define ST_BH 24576
#define ST_BL 28928              // +16*136*2
#define ST_SZ 33280
#define GSMEM (2 * ST_SZ)        // 66560

template <int EPI>
__global__ __launch_bounds__(256, 1) void tgemm(
    const __nv_bfloat16* __restrict__ Ah, const __nv_bfloat16* __restrict__ Al,
    const __nv_bfloat16* __restrict__ Bh, const __nv_bfloat16* __restrict__ Bl,
    const float* __restrict__ bias, float* __restrict__ C,
    __nv_bfloat16* __restrict__ Ch, __nv_bfloat16* __restrict__ Cl,
    int M, int N, int K)
{
    extern __shared__ char smem[];

    const int tid  = threadIdx.x;
    const int lane = tid & 31;
    const int w    = tid >> 5;
    const int wm   = w & 3;     // 4 m-groups of 64 rows
    const int wn   = w >> 2;    // 2 n-groups of 64 cols
    const int bm   = blockIdx.y * 256;
    const int bn   = blockIdx.x * 128;

    // loaders: A -> thread = row tid, 16 elems (2 x uint4) per matrix
    //          B -> thread = (krow, 8-col chunk) per matrix
    const int br = tid >> 4;          // 0..15
    const int bc = (tid & 15) * 8;    // 0..120

    const __nv_bfloat16* gAh = Ah + (size_t)(bm + tid) * K;
    const __nv_bfloat16* gAl = Al + (size_t)(bm + tid) * K;
    const __nv_bfloat16* gBh = Bh + (size_t)br * N + bn + bc;
    const __nv_bfloat16* gBl = Bl + (size_t)br * N + bn + bc;

    // smem byte offsets for this thread's stores
    const uint32_t oA = (uint32_t)(tid * ASTR) * 2;
    const uint32_t oB = (uint32_t)(br * BSTR + bc) * 2;

    // ldmatrix byte offsets within a stage
    int a_off[4];
#pragma unroll
    for (int mi = 0; mi < 4; mi++) {
        int row = wm * 64 + mi * 16 + (lane & 15);
        int col = (lane >> 4) * 8;
        a_off[mi] = (row * ASTR + col) * 2;
    }
    int b_off[4];
    {
        int krow = lane & 15;
#pragma unroll
        for (int p = 0; p < 4; p++) {
            int col = wn * 64 + (p * 2 + (lane >> 4)) * 8;
            b_off[p] = (krow * BSTR + col) * 2;
        }
    }

    float c[4][8][4];
#pragma unroll
    for (int mi = 0; mi < 4; mi++)
#pragma unroll
        for (int ni = 0; ni < 8; ni++)
#pragma unroll
            for (int e = 0; e < 4; e++) c[mi][ni][e] = 0.f;

    // prologue: tile 0 -> buf 0
    {
        uint4 a0 = *(const uint4*)(gAh);
        uint4 a1 = *(const uint4*)(gAh + 8);
        uint4 a2 = *(const uint4*)(gAl);
        uint4 a3 = *(const uint4*)(gAl + 8);
        uint4 b0 = *(const uint4*)(gBh);
        uint4 b1 = *(const uint4*)(gBl);
        *(uint4*)(smem + ST_AH + oA)      = a0;
        *(uint4*)(smem + ST_AH + oA + 16) = a1;
        *(uint4*)(smem + ST_AL + oA)      = a2;
        *(uint4*)(smem + ST_AL + oA + 16) = a3;
        *(uint4*)(smem + ST_BH + oB)      = b0;
        *(uint4*)(smem + ST_BL + oB)      = b1;
    }
    __syncthreads();

    const int nk = K >> 4;
    uint4 pa0, pa1, pa2, pa3, pb0, pb1;
    for (int kt = 0; kt < nk; kt++) {
        const uint32_t sbuf = (uint32_t)(kt & 1) * ST_SZ;
        if (kt + 1 < nk) {
            int k0 = (kt + 1) * 16;
            pa0 = *(const uint4*)(gAh + k0);
            pa1 = *(const uint4*)(gAh + k0 + 8);
            pa2 = *(const uint4*)(gAl + k0);
            pa3 = *(const uint4*)(gAl + k0 + 8);
            pb0 = *(const uint4*)(gBh + (size_t)k0 * N);
            pb1 = *(const uint4*)(gBl + (size_t)k0 * N);
        }

        const char* stg = smem + sbuf;
        uint32_t fah[4][4], fal[4][4], fb[8][2];
#pragma unroll
        for (int mi = 0; mi < 4; mi++) {
            ldsm4(fah[mi], stg + ST_AH + a_off[mi]);
            ldsm4(fal[mi], stg + ST_AL + a_off[mi]);
        }
        // B hi
#pragma unroll
        for (int p = 0; p < 4; p++) {
            uint32_t r[4];
            ldsm4t(r, stg + ST_BH + b_off[p]);
            fb[p * 2][0] = r[0]; fb[p * 2][1] = r[1];
            fb[p * 2 + 1][0] = r[2]; fb[p * 2 + 1][1] = r[3];
        }
#pragma unroll
        for (int mi = 0; mi < 4; mi++)
#pragma unroll
            for (int ni = 0; ni < 8; ni++) mma16816(c[mi][ni], fah[mi], fb[ni]);  // hh
#pragma unroll
        for (int mi = 0; mi < 4; mi++)
#pragma unroll
            for (int ni = 0; ni < 8; ni++) mma16816(c[mi][ni], fal[mi], fb[ni]);  // lh
        // B lo (reuse fb)
#pragma unroll
        for (int p = 0; p < 4; p++) {
            uint32_t r[4];
            ldsm4t(r, stg + ST_BL + b_off[p]);
            fb[p * 2][0] = r[0]; fb[p * 2][1] = r[1];
            fb[p * 2 + 1][0] = r[2]; fb[p * 2 + 1][1] = r[3];
        }
#pragma unroll
        for (int mi = 0; mi < 4; mi++)
#pragma unroll
            for (int ni = 0; ni < 8; ni++) mma16816(c[mi][ni], fah[mi], fb[ni]);  // hl

        if (kt + 1 < nk) {
            const uint32_t nb = (uint32_t)((kt + 1) & 1) * ST_SZ;
            *(uint4*)(smem + nb + ST_AH + oA)      = pa0;
            *(uint4*)(smem + nb + ST_AH + oA + 16) = pa1;
            *(uint4*)(smem + nb + ST_AL + oA)      = pa2;
            *(uint4*)(smem + nb + ST_AL + oA + 16) = pa3;
            *(uint4*)(smem + nb + ST_BH + oB)      = pb0;
            *(uint4*)(smem + nb + ST_BL + oB)      = pb1;
            __syncthreads();
        }
    }

    // epilogue
    const int er = lane >> 2;
    const int ec = (lane & 3) * 2;
#pragma unroll
    for (int mi = 0; mi < 4; mi++) {
#pragma unroll
        for (int ni = 0; ni < 8; ni++) {
            int r0 = bm + wm * 64 + mi * 16 + er;
            int cc = bn + wn * 64 + ni * 8 + ec;
            float v0 = c[mi][ni][0], v1 = c[mi][ni][1];
            float v2 = c[mi][ni][2], v3 = c[mi][ni][3];
            if (EPI >= 1) {
                float bi0 = bias[cc], bi1 = bias[cc + 1];
                v0 += bi0; v1 += bi1; v2 += bi0; v3 += bi1;
            }
            if (EPI == 3) {
                v0 = fmaxf(v0, 0.f); v1 = fmaxf(v1, 0.f);
                v2 = fmaxf(v2, 0.f); v3 = fmaxf(v3, 0.f);
                __nv_bfloat16 h0 = __float2bfloat16(v0);
                __nv_bfloat16 h1 = __float2bfloat16(v1);
                __nv_bfloat16 h2 = __float2bfloat16(v2);
                __nv_bfloat16 h3 = __float2bfloat16(v3);
                __nv_bfloat162 hp0; hp0.x = h0; hp0.y = h1;
                __nv_bfloat162 hp1; hp1.x = h2; hp1.y = h3;
                __nv_bfloat162 lp0;
                lp0.x = __float2bfloat16(v0 - __bfloat162float(h0));
                lp0.y = __float2bfloat16(v1 - __bfloat162float(h1));
                __nv_bfloat162 lp1;
                lp1.x = __float2bfloat16(v2 - __bfloat162float(h2));
                lp1.y = __float2bfloat16(v3 - __bfloat162float(h3));
                *reinterpret_cast<__nv_bfloat162*>(&Ch[(size_t)r0 * N + cc])       = hp0;
                *reinterpret_cast<__nv_bfloat162*>(&Cl[(size_t)r0 * N + cc])       = lp0;
                *reinterpret_cast<__nv_bfloat162*>(&Ch[(size_t)(r0 + 8) * N + cc]) = hp1;
                *reinterpret_cast<__nv_bfloat162*>(&Cl[(size_t)(r0 + 8) * N + cc]) = lp1;
            } else {
                *(float2*)&C[(size_t)r0 * N + cc]       = make_float2(v0, v1);
                *(float2*)&C[(size_t)(r0 + 8) * N + cc] = make_float2(v2, v3);
            }
        }
    }
}

// ===========================================================================
// Attention (fp32 SIMT) reading fused QKV [NTOK, 2304]; ctx -> bf16 split.
// ===========================================================================
__global__ __launch_bounds__(256) void attn_kernel(
    const float* __restrict__ QKV,
    __nv_bfloat16* __restrict__ Oh, __nv_bfloat16* __restrict__ Ol)
{
    extern __shared__ float sm[];
    float* sQ  = sm;
    float* sK  = sQ + 2048;
    float* sKt = sK + 4096;
    float* sS  = sKt + 4352;

    const int qt  = blockIdx.x;
    const int h   = blockIdx.y;
    const int b   = blockIdx.z;
    const int tid = threadIdx.x;
    const size_t base = (size_t)b * SEQ * QKVN + h * DK;

    for (int i = tid; i < 512; i += 256) {
        int r = i >> 4, cx = (i & 15) * 4;
        *(float4*)&sQ[r * 64 + cx] =
            *(const float4*)&QKV[base + (size_t)(qt * 32 + r) * QKVN + cx];
    }

    const int gq  = tid >> 4;
    const int gk  = tid & 15;
    const int qi0 = gq * 2;
    const int kj0 = gk * 4;

    for (int kt = 0; kt < 8; kt++) {
        __syncthreads();
        for (int i = tid; i < 1024; i += 256) {
            int r = i >> 4, cx = (i & 15) * 4;
            *(float4*)&sK[r * 64 + cx] =
                *(const float4*)&QKV[base + 768 + (size_t)(kt * 64 + r) * QKVN + cx];
        }
        __syncthreads();
        for (int i = tid; i < 4096; i += 256) {
            int d = i & 63, r = i >> 6;
            sKt[d * 68 + r] = sK[r * 64 + d];
        }
        __syncthreads();

        float acc[2][4] = {{0.f,0.f,0.f,0.f},{0.f,0.f,0.f,0.f}};
#pragma unroll 8
        for (int d = 0; d < 64; d++) {
            float q0 = sQ[qi0 * 64 + d];
            float q1 = sQ[qi0 * 64 + 64 + d];
            float4 kv = *(float4*)&sKt[d * 68 + kj0];
            acc[0][0] += q0 * kv.x; acc[0][1] += q0 * kv.y;
            acc[0][2] += q0 * kv.z; acc[0][3] += q0 * kv.w;
            acc[1][0] += q1 * kv.x; acc[1][1] += q1 * kv.y;
            acc[1][2] += q1 * kv.z; acc[1][3] += q1 * kv.w;
        }
#pragma unroll
        for (int i = 0; i < 2; i++)
#pragma unroll
            for (int j = 0; j < 4; j++)
                sS[(qi0 + i) * 512 + kt * 64 + kj0 + j] = acc[i][j] * 0.125f;
    }
    __syncthreads();

    {
        const int wid = tid >> 5, lanei = tid & 31;
        for (int r = wid * 4; r < wid * 4 + 4; r++) {
            float* srow = sS + r * 512;
            float m = -1e30f;
            for (int cx = lanei; cx < 512; cx += 32) m = fmaxf(m, srow[cx]);
#pragma unroll
            for (int o = 16; o > 0; o >>= 1)
                m = fmaxf(m, __shfl_xor_sync(0xffffffffu, m, o));
            float s = 0.f;
            for (int cx = lanei; cx < 512; cx += 32) {
                float e = __expf(srow[cx] - m);
                srow[cx] = e;
                s += e;
            }
#pragma unroll
            for (int o = 16; o > 0; o >>= 1)
                s += __shfl_xor_sync(0xffffffffu, s, o);
            float inv = 1.0f / s;
            for (int cx = lanei; cx < 512; cx += 32) srow[cx] *= inv;
        }
    }

    const int d0 = gk * 4;
    float o_[2][4] = {{0.f,0.f,0.f,0.f},{0.f,0.f,0.f,0.f}};
    for (int kt = 0; kt < 8; kt++) {
        __syncthreads();
        for (int i = tid; i < 1024; i += 256) {
            int r = i >> 4, cx = (i & 15) * 4;
            *(float4*)&sK[r * 64 + cx] =
                *(const float4*)&QKV[base + 1536 + (size_t)(kt * 64 + r) * QKVN + cx];
        }
        __syncthreads();
#pragma unroll 4
        for (int k = 0; k < 64; k++) {
            float s0 = sS[qi0 * 512 + kt * 64 + k];
            float s1 = sS[qi0 * 512 + 512 + kt * 64 + k];
            float4 vv = *(float4*)&sK[k * 64 + d0];
            o_[0][0] += s0 * vv.x; o_[0][1] += s0 * vv.y;
            o_[0][2] += s0 * vv.z; o_[0][3] += s0 * vv.w;
            o_[1][0] += s1 * vv.x; o_[1][1] += s1 * vv.y;
            o_[1][2] += s1 * vv.z; o_[1][3] += s1 * vv.w;
        }
    }

#pragma unroll
    for (int i = 0; i < 2; i++) {
        size_t idx = ((size_t)b * SEQ + qt * 32 + qi0 + i) * EMB + h * DK + d0;
        __nv_bfloat16 h0 = __float2bfloat16(o_[i][0]);
        __nv_bfloat16 h1 = __float2bfloat16(o_[i][1]);
        __nv_bfloat16 h2 = __float2bfloat16(o_[i][2]);
        __nv_bfloat16 h3 = __float2bfloat16(o_[i][3]);
        __nv_bfloat162 hp0; hp0.x = h0; hp0.y = h1;
        __nv_bfloat162 hp1; hp1.x = h2; hp1.y = h3;
        __nv_bfloat162 lp0;
        lp0.x = __float2bfloat16(o_[i][0] - __bfloat162float(h0));
        lp0.y = __float2bfloat16(o_[i][1] - __bfloat162float(h1));
        __nv_bfloat162 lp1;
        lp1.x = __float2bfloat16(o_[i][2] - __bfloat162float(h2));
        lp1.y = __float2bfloat16(o_[i][3] - __bfloat162float(h3));
        *reinterpret_cast<__nv_bfloat162*>(&Oh[idx])     = hp0;
        *reinterpret_cast<__nv_bfloat162*>(&Oh[idx + 2]) = hp1;
        *reinterpret_cast<__nv_bfloat162*>(&Ol[idx])     = lp0;
        *reinterpret_cast<__nv_bfloat162*>(&Ol[idx + 2]) = lp1;
    }
}

// ===========================================================================
// Fused residual + LayerNorm (+ optional bf16 split out)
// ===========================================================================
__global__ __launch_bounds__(256) void add_ln_kernel(
    const float* __restrict__ x, const float* __restrict__ r,
    const float* __restrict__ gamma, const float* __restrict__ beta,
    float* __restrict__ out,
    __nv_bfloat16* __restrict__ oh, __nv_bfloat16* __restrict__ ol)
{
    const int row = blockIdx.x;
    const int tid = threadIdx.x;
    const float* xr = x + (size_t)row * EMB;
    const float* rr = r + (size_t)row * EMB;

    float v[3];
    float s = 0.f;
#pragma unroll
    for (int i = 0; i < 3; i++) {
        int cx = tid + i * 256;
        float t = xr[cx] + rr[cx];
        v[i] = t;
        s += t;
    }

    __shared__ float red[8];
    const int wid = tid >> 5, lane = tid & 31;
#pragma unroll
    for (int o = 16; o > 0; o >>= 1) s += __shfl_xor_sync(0xffffffffu, s, o);
    if (lane == 0) red[wid] = s;
    __syncthreads();
    if (tid == 0) {
        float t = 0.f;
#pragma unroll
        for (int i = 0; i < 8; i++) t += red[i];
        red[0] = t;
    }
    __syncthreads();
    const float mean = red[0] * (1.0f / 768.0f);

    float s2 = 0.f;
#pragma unroll
    for (int i = 0; i < 3; i++) {
        float d = v[i] - mean;
        s2 += d * d;
    }
#pragma unroll
    for (int o = 16; o > 0; o >>= 1) s2 += __shfl_xor_sync(0xffffffffu, s2, o);
    __syncthreads();
    if (lane == 0) red[wid] = s2;
    __syncthreads();
    if (tid == 0) {
        float t = 0.f;
#pragma unroll
        for (int i = 0; i < 8; i++) t += red[i];
        red[0] = t;
    }
    __syncthreads();
    const float var  = red[0] * (1.0f / 768.0f);
    const float rstd = rsqrtf(var + 1e-5f);

#pragma unroll
    for (int i = 0; i < 3; i++) {
        int cx = tid + i * 256;
        float o = (v[i] - mean) * rstd * gamma[cx] + beta[cx];
        size_t idx = (size_t)row * EMB + cx;
        out[idx] = o;
        if (oh) {
            __nv_bfloat16 hh = __float2bfloat16(o);
            oh[idx] = hh;
            ol[idx] = __float2bfloat16(o - __bfloat162float(hh));
        }
    }
}

// ===========================================================================
// Launch
// ===========================================================================
extern "C" void kernel_launch(void* const* d_in, const int* in_sizes, int n_in,
                              void* d_out, int out_size)
{
    (void)in_sizes; (void)n_in; (void)out_size;

    const float* x   = (const float*)d_in[0];
    const float* Wq  = (const float*)d_in[1];
    const float* Wk  = (const float*)d_in[2];
    const float* Wv  = (const float*)d_in[3];
    const float* Wo  = (const float*)d_in[4];
    const float* W1  = (const float*)d_in[5];
    const float* b1  = (const float*)d_in[6];
    const float* W2  = (const float*)d_in[7];
    const float* b2  = (const float*)d_in[8];
    const float* g1  = (const float*)d_in[9];
    const float* be1 = (const float*)d_in[10];
    const float* g2  = (const float*)d_in[11];
    const float* be2 = (const float*)d_in[12];
    float* out = (float*)d_out;

    float *qkv, *tmp, *x1;
    __nv_bfloat16 *ah, *al, *ch, *cl, *fh, *fl, *wh, *wl;
    cudaGetSymbolAddress((void**)&qkv, g_qkv);
    cudaGetSymbolAddress((void**)&tmp, g_tmp);
    cudaGetSymbolAddress((void**)&x1,  g_x1);
    cudaGetSymbolAddress((void**)&ah,  g_ah);
    cudaGetSymbolAddress((void**)&al,  g_al);
    cudaGetSymbolAddress((void**)&ch,  g_ch);
    cudaGetSymbolAddress((void**)&cl,  g_cl);
    cudaGetSymbolAddress((void**)&fh,  g_fh);
    cudaGetSymbolAddress((void**)&fl,  g_fl);
    cudaGetSymbolAddress((void**)&wh,  g_wh);
    cudaGetSymbolAddress((void**)&wl,  g_wl);

    const int ATTN_SMEM = (2048 + 4096 + 64 * 68 + 16384) * 4;
    cudaFuncSetAttribute(attn_kernel,
                         cudaFuncAttributeMaxDynamicSharedMemorySize, ATTN_SMEM);
    cudaFuncSetAttribute(tgemm<0>,
                         cudaFuncAttributeMaxDynamicSharedMemorySize, GSMEM);
    cudaFuncSetAttribute(tgemm<1>,
                         cudaFuncAttributeMaxDynamicSharedMemorySize, GSMEM);
    cudaFuncSetAttribute(tgemm<3>,
                         cudaFuncAttributeMaxDynamicSharedMemorySize, GSMEM);

    const size_t EE = (size_t)EMB * EMB;
    const size_t EF = (size_t)EMB * FFND;
    const size_t OQKV = 0, OO_ = 3 * EE, O1_ = 4 * EE, O2_ = 4 * EE + EF;

    dim3 blk(256);

    // activation split (x)
    split_kernel<<<NTOK * EMB / 1024, blk>>>(x, ah, al, NTOK * EMB);
    // weight splits; Wq/Wk/Wv scatter into merged [768,2304] buffer
    splitw_kernel<<<(int)(EE / 1024), blk>>>(Wq, wh + OQKV, wl + OQKV, EMB, QKVN, 0,    (int)EE);
    splitw_kernel<<<(int)(EE / 1024), blk>>>(Wk, wh + OQKV, wl + OQKV, EMB, QKVN, 768,  (int)EE);
    splitw_kernel<<<(int)(EE / 1024), blk>>>(Wv, wh + OQKV, wl + OQKV, EMB, QKVN, 1536, (int)EE);
    splitw_kernel<<<(int)(EE / 1024), blk>>>(Wo, wh + OO_,  wl + OO_,  EMB, EMB,  0,    (int)EE);
    splitw_kernel<<<(int)(EF / 1024), blk>>>(W1, wh + O1_,  wl + O1_,  FFND, FFND, 0,   (int)EF);
    splitw_kernel<<<(int)(EF / 1024), blk>>>(W2, wh + O2_,  wl + O2_,  EMB,  EMB,  0,   (int)EF);

    // fused QKV projection: [NTOK,768] @ [768,2304]
    tgemm<0><<<dim3(QKVN / 128, NTOK / 256), blk, GSMEM>>>(
        ah, al, wh + OQKV, wl + OQKV, nullptr, qkv, nullptr, nullptr, NTOK, QKVN, EMB);

    // attention -> ctx (bf16 split)
    attn_kernel<<<dim3(SEQ / 32, HEADS, BATCH), blk, ATTN_SMEM>>>(qkv, ch, cl);

    // output projection
    tgemm<0><<<dim3(EMB / 128, NTOK / 256), blk, GSMEM>>>(
        ch, cl, wh + OO_, wl + OO_, nullptr, tmp, nullptr, nullptr, NTOK, EMB, EMB);

    // residual + LN1 (emits x1 split into ah/al)
    add_ln_kernel<<<NTOK, blk>>>(x, tmp, g1, be1, x1, ah, al);

    // FFN
    tgemm<3><<<dim3(FFND / 128, NTOK / 256), blk, GSMEM>>>(
        ah, al, wh + O1_, wl + O1_, b1, nullptr, fh, fl, NTOK, FFND, EMB);
    tgemm<1><<<dim3(EMB / 128, NTOK / 256), blk, GSMEM>>>(
        fh, fl, wh + O2_, wl + O2_, b2, tmp, nullptr, nullptr, NTOK, EMB, FFND);

    // residual + LN2
    add_ln_kernel<<<NTOK, blk>>>(x1, tmp, g2, be2, out, nullptr, nullptr);
}

// round 8
// speedup vs baseline: 1.6849x; 1.5466x over previous
#include <cuda_runtime.h>
#include <cuda_fp16.h>
#include <cstdint>

// ---------------------------------------------------------------------------
// ViT encoder block. GEMMs: single-pass fp16 mma.sync (fp32 accumulate),
// 128x128 CTA tile, 32x64 warp tile, register-prefetch double-buffered smem.
// Merged QKV. Attention + LayerNorm fp32 SIMT.
// ---------------------------------------------------------------------------

#define NTOK   16384
#define EMB    768
#define FFND   3072
#define HEADS  12
#define DK     64
#define SEQ    512
#define BATCH  32
#define QKVN   2304

// ----- fp32 scratch -----
__device__ __align__(128) float g_qkv[NTOK * QKVN];
__device__ __align__(128) float g_tmp[NTOK * EMB];
__device__ __align__(128) float g_x1 [NTOK * EMB];

// ----- fp16 scratch -----
__device__ __align__(128) __half g_ah[NTOK * EMB];    // activations (x, then x1)
__device__ __align__(128) __half g_ch[NTOK * EMB];    // ctx
__device__ __align__(128) __half g_fh[NTOK * FFND];   // relu(ffn)
#define WTOT 7077888
__device__ __align__(128) __half g_wh[WTOT];          // all weights, QKV merged

// ===========================================================================
// helpers
// ===========================================================================
__device__ __forceinline__ void ldsm4(uint32_t* r, const void* p) {
    uint32_t a = (uint32_t)__cvta_generic_to_shared(p);
    asm volatile("ldmatrix.sync.aligned.m8n8.x4.shared.b16 {%0,%1,%2,%3}, [%4];"
                 : "=r"(r[0]), "=r"(r[1]), "=r"(r[2]), "=r"(r[3]) : "r"(a));
}
__device__ __forceinline__ void ldsm4t(uint32_t* r, const void* p) {
    uint32_t a = (uint32_t)__cvta_generic_to_shared(p);
    asm volatile("ldmatrix.sync.aligned.m8n8.x4.trans.shared.b16 {%0,%1,%2,%3}, [%4];"
                 : "=r"(r[0]), "=r"(r[1]), "=r"(r[2]), "=r"(r[3]) : "r"(a));
}
__device__ __forceinline__ void mma16816(float* c, const uint32_t* a, const uint32_t* b) {
    asm volatile("mma.sync.aligned.m16n8k16.row.col.f32.f16.f16.f32 "
                 "{%0,%1,%2,%3}, {%4,%5,%6,%7}, {%8,%9}, {%0,%1,%2,%3};"
                 : "+f"(c[0]), "+f"(c[1]), "+f"(c[2]), "+f"(c[3])
                 : "r"(a[0]), "r"(a[1]), "r"(a[2]), "r"(a[3]), "r"(b[0]), "r"(b[1]));
}

// ===========================================================================
// cvt: fp32 -> fp16 (contiguous, for activations)
// ===========================================================================
__global__ __launch_bounds__(256) void cvt_kernel(
    const float* __restrict__ in, __half* __restrict__ h, int n)
{
    int i = (blockIdx.x * 256 + threadIdx.x) * 8;
    if (i >= n) return;
    float4 v0 = *(const float4*)(in + i);
    float4 v1 = *(const float4*)(in + i + 4);
    __half2 a = __floats2half2_rn(v0.x, v0.y);
    __half2 b = __floats2half2_rn(v0.z, v0.w);
    __half2 c = __floats2half2_rn(v1.x, v1.y);
    __half2 d = __floats2half2_rn(v1.z, v1.w);
    *reinterpret_cast<__half2*>(h + i)     = a;
    *reinterpret_cast<__half2*>(h + i + 2) = b;
    *reinterpret_cast<__half2*>(h + i + 4) = c;
    *reinterpret_cast<__half2*>(h + i + 6) = d;
}

// ===========================================================================
// cvtw: W[K,N] fp32 -> fp16 at column offset `off` of width-Ntot buffer
// ===========================================================================
__global__ __launch_bounds__(256) void cvtw_kernel(
    const float* __restrict__ W, __half* __restrict__ h,
    int N, int Ntot, int off, int total)
{
    int i = (blockIdx.x * 256 + threadIdx.x) * 4;
    if (i >= total) return;
    int k = i / N, n = i - k * N;
    size_t o = (size_t)k * Ntot + off + n;
    float4 v = *(const float4*)(W + i);
    __half2 a = __floats2half2_rn(v.x, v.y);
    __half2 b = __floats2half2_rn(v.z, v.w);
    *reinterpret_cast<__half2*>(h + o)     = a;
    *reinterpret_cast<__half2*>(h + o + 2) = b;
}

// ===========================================================================
// GEMM: C[M,N] = A[M,K] @ B[K,N]; A/B fp16. 128x128 tile, BK=16,
// 256 threads (4x2 warps, 32x64 per warp), register prefetch + double buffer.
// EPI: 0 = fp32 C; 1 = +bias fp32 C; 3 = +bias+relu -> fp16 Ch
// ===========================================================================
#define ASTR 24    // A smem row stride (elems)
#define BSTR 136   // B smem row stride (elems)

template <int EPI>
__global__ __launch_bounds__(256) void tgemm(
    const __half* __restrict__ A, const __half* __restrict__ B,
    const float* __restrict__ bias, float* __restrict__ C,
    __half* __restrict__ Ch,
    int M, int N, int K)
{
    __shared__ __align__(16) __half sA[2][128 * ASTR];
    __shared__ __align__(16) __half sB[2][16 * BSTR];

    const int tid  = threadIdx.x;
    const int lane = tid & 31;
    const int w    = tid >> 5;
    const int wm   = w & 3;
    const int wn   = w >> 2;
    const int bm   = blockIdx.y * 128;
    const int bn   = blockIdx.x * 128;

    const int ar  = tid >> 1;
    const int acg = (tid & 1) * 8;
    const int br  = tid >> 4;
    const int bc  = (tid & 15) * 8;

    const __half* gA = A + (size_t)(bm + ar) * K + acg;
    const __half* gB = B + (size_t)br * N + bn + bc;

    int a_off[2];
#pragma unroll
    for (int mi = 0; mi < 2; mi++) {
        int row = wm * 32 + mi * 16 + (lane & 15);
        int col = (lane >> 4) * 8;
        a_off[mi] = row * ASTR + col;
    }
    int b_off[4];
    {
        int krow = lane & 15;
#pragma unroll
        for (int p = 0; p < 4; p++) {
            int col = wn * 64 + (p * 2 + (lane >> 4)) * 8;
            b_off[p] = krow * BSTR + col;
        }
    }

    float c[2][8][4];
#pragma unroll
    for (int mi = 0; mi < 2; mi++)
#pragma unroll
        for (int ni = 0; ni < 8; ni++)
#pragma unroll
            for (int e = 0; e < 4; e++) c[mi][ni][e] = 0.f;

    // prologue: tile 0 -> buf 0
    {
        uint4 va = *(const uint4*)gA;
        uint4 vb = *(const uint4*)gB;
        *(uint4*)&sA[0][ar * ASTR + acg] = va;
        *(uint4*)&sB[0][br * BSTR + bc]  = vb;
    }
    __syncthreads();

    const int nk = K >> 4;
    uint4 pa, pb;
    for (int kt = 0; kt < nk; kt++) {
        const int buf = kt & 1;
        if (kt + 1 < nk) {
            int k0 = (kt + 1) * 16;
            pa = *(const uint4*)(gA + k0);
            pb = *(const uint4*)(gB + (size_t)k0 * N);
        }

        uint32_t fa[2][4], fb[8][2];
#pragma unroll
        for (int mi = 0; mi < 2; mi++) ldsm4(fa[mi], &sA[buf][a_off[mi]]);
#pragma unroll
        for (int p = 0; p < 4; p++) {
            uint32_t r[4];
            ldsm4t(r, &sB[buf][b_off[p]]);
            fb[p * 2][0] = r[0]; fb[p * 2][1] = r[1];
            fb[p * 2 + 1][0] = r[2]; fb[p * 2 + 1][1] = r[3];
        }

#pragma unroll
        for (int mi = 0; mi < 2; mi++)
#pragma unroll
            for (int ni = 0; ni < 8; ni++) mma16816(c[mi][ni], fa[mi], fb[ni]);

        if (kt + 1 < nk) {
            const int nb = buf ^ 1;
            *(uint4*)&sA[nb][ar * ASTR + acg] = pa;
            *(uint4*)&sB[nb][br * BSTR + bc]  = pb;
            __syncthreads();
        }
    }

    // epilogue
    const int er = lane >> 2;
    const int ec = (lane & 3) * 2;
#pragma unroll
    for (int mi = 0; mi < 2; mi++) {
#pragma unroll
        for (int ni = 0; ni < 8; ni++) {
            int r0 = bm + wm * 32 + mi * 16 + er;
            int cc = bn + wn * 64 + ni * 8 + ec;
            float v0 = c[mi][ni][0], v1 = c[mi][ni][1];
            float v2 = c[mi][ni][2], v3 = c[mi][ni][3];
            if (EPI >= 1) {
                float bi0 = bias[cc], bi1 = bias[cc + 1];
                v0 += bi0; v1 += bi1; v2 += bi0; v3 += bi1;
            }
            if (EPI == 3) {
                v0 = fmaxf(v0, 0.f); v1 = fmaxf(v1, 0.f);
                v2 = fmaxf(v2, 0.f); v3 = fmaxf(v3, 0.f);
                *reinterpret_cast<__half2*>(&Ch[(size_t)r0 * N + cc]) =
                    __floats2half2_rn(v0, v1);
                *reinterpret_cast<__half2*>(&Ch[(size_t)(r0 + 8) * N + cc]) =
                    __floats2half2_rn(v2, v3);
            } else {
                *(float2*)&C[(size_t)r0 * N + cc]       = make_float2(v0, v1);
                *(float2*)&C[(size_t)(r0 + 8) * N + cc] = make_float2(v2, v3);
            }
        }
    }
}

// ===========================================================================
// Attention (fp32 SIMT) reading fused QKV [NTOK, 2304]; ctx -> fp16.
// ===========================================================================
__global__ __launch_bounds__(256) void attn_kernel(
    const float* __restrict__ QKV, __half* __restrict__ Oh)
{
    extern __shared__ float sm[];
    float* sQ  = sm;
    float* sK  = sQ + 2048;
    float* sKt = sK + 4096;
    float* sS  = sKt + 4352;

    const int qt  = blockIdx.x;
    const int h   = blockIdx.y;
    const int b   = blockIdx.z;
    const int tid = threadIdx.x;
    const size_t base = (size_t)b * SEQ * QKVN + h * DK;

    for (int i = tid; i < 512; i += 256) {
        int r = i >> 4, cx = (i & 15) * 4;
        *(float4*)&sQ[r * 64 + cx] =
            *(const float4*)&QKV[base + (size_t)(qt * 32 + r) * QKVN + cx];
    }

    const int gq  = tid >> 4;
    const int gk  = tid & 15;
    const int qi0 = gq * 2;
    const int kj0 = gk * 4;

    for (int kt = 0; kt < 8; kt++) {
        __syncthreads();
        for (int i = tid; i < 1024; i += 256) {
            int r = i >> 4, cx = (i & 15) * 4;
            *(float4*)&sK[r * 64 + cx] =
                *(const float4*)&QKV[base + 768 + (size_t)(kt * 64 + r) * QKVN + cx];
        }
        __syncthreads();
        for (int i = tid; i < 4096; i += 256) {
            int d = i & 63, r = i >> 6;
            sKt[d * 68 + r] = sK[r * 64 + d];
        }
        __syncthreads();

        float acc[2][4] = {{0.f,0.f,0.f,0.f},{0.f,0.f,0.f,0.f}};
#pragma unroll 8
        for (int d = 0; d < 64; d++) {
            float q0 = sQ[qi0 * 64 + d];
            float q1 = sQ[qi0 * 64 + 64 + d];
            float4 kv = *(float4*)&sKt[d * 68 + kj0];
            acc[0][0] += q0 * kv.x; acc[0][1] += q0 * kv.y;
            acc[0][2] += q0 * kv.z; acc[0][3] += q0 * kv.w;
            acc[1][0] += q1 * kv.x; acc[1][1] += q1 * kv.y;
            acc[1][2] += q1 * kv.z; acc[1][3] += q1 * kv.w;
        }
#pragma unroll
        for (int i = 0; i < 2; i++)
#pragma unroll
            for (int j = 0; j < 4; j++)
                sS[(qi0 + i) * 512 + kt * 64 + kj0 + j] = acc[i][j] * 0.125f;
    }
    __syncthreads();

    {
        const int wid = tid >> 5, lanei = tid & 31;
        for (int r = wid * 4; r < wid * 4 + 4; r++) {
            float* srow = sS + r * 512;
            float m = -1e30f;
            for (int cx = lanei; cx < 512; cx += 32) m = fmaxf(m, srow[cx]);
#pragma unroll
            for (int o = 16; o > 0; o >>= 1)
                m = fmaxf(m, __shfl_xor_sync(0xffffffffu, m, o));
            float s = 0.f;
            for (int cx = lanei; cx < 512; cx += 32) {
                float e = __expf(srow[cx] - m);
                srow[cx] = e;
                s += e;
            }
#pragma unroll
            for (int o = 16; o > 0; o >>= 1)
                s += __shfl_xor_sync(0xffffffffu, s, o);
            float inv = 1.0f / s;
            for (int cx = lanei; cx < 512; cx += 32) srow[cx] *= inv;
        }
    }

    const int d0 = gk * 4;
    float o_[2][4] = {{0.f,0.f,0.f,0.f},{0.f,0.f,0.f,0.f}};
    for (int kt = 0; kt < 8; kt++) {
        __syncthreads();
        for (int i = tid; i < 1024; i += 256) {
            int r = i >> 4, cx = (i & 15) * 4;
            *(float4*)&sK[r * 64 + cx] =
                *(const float4*)&QKV[base + 1536 + (size_t)(kt * 64 + r) * QKVN + cx];
        }
        __syncthreads();
#pragma unroll 4
        for (int k = 0; k < 64; k++) {
            float s0 = sS[qi0 * 512 + kt * 64 + k];
            float s1 = sS[qi0 * 512 + 512 + kt * 64 + k];
            float4 vv = *(float4*)&sK[k * 64 + d0];
            o_[0][0] += s0 * vv.x; o_[0][1] += s0 * vv.y;
            o_[0][2] += s0 * vv.z; o_[0][3] += s0 * vv.w;
            o_[1][0] += s1 * vv.x; o_[1][1] += s1 * vv.y;
            o_[1][2] += s1 * vv.z; o_[1][3] += s1 * vv.w;
        }
    }

#pragma unroll
    for (int i = 0; i < 2; i++) {
        size_t idx = ((size_t)b * SEQ + qt * 32 + qi0 + i) * EMB + h * DK + d0;
        *reinterpret_cast<__half2*>(&Oh[idx])     = __floats2half2_rn(o_[i][0], o_[i][1]);
        *reinterpret_cast<__half2*>(&Oh[idx + 2]) = __floats2half2_rn(o_[i][2], o_[i][3]);
    }
}

// ===========================================================================
// Fused residual + LayerNorm (+ optional fp16 out)
// ===========================================================================
__global__ __launch_bounds__(256) void add_ln_kernel(
    const float* __restrict__ x, const float* __restrict__ r,
    const float* __restrict__ gamma, const float* __restrict__ beta,
    float* __restrict__ out, __half* __restrict__ oh)
{
    const int row = blockIdx.x;
    const int tid = threadIdx.x;
    const float* xr = x + (size_t)row * EMB;
    const float* rr = r + (size_t)row * EMB;

    float v[3];
    float s = 0.f;
#pragma unroll
    for (int i = 0; i < 3; i++) {
        int cx = tid + i * 256;
        float t = xr[cx] + rr[cx];
        v[i] = t;
        s += t;
    }

    __shared__ float red[8];
    const int wid = tid >> 5, lane = tid & 31;
#pragma unroll
    for (int o = 16; o > 0; o >>= 1) s += __shfl_xor_sync(0xffffffffu, s, o);
    if (lane == 0) red[wid] = s;
    __syncthreads();
    if (tid == 0) {
        float t = 0.f;
#pragma unroll
        for (int i = 0; i < 8; i++) t += red[i];
        red[0] = t;
    }
    __syncthreads();
    const float mean = red[0] * (1.0f / 768.0f);

    float s2 = 0.f;
#pragma unroll
    for (int i = 0; i < 3; i++) {
        float d = v[i] - mean;
        s2 += d * d;
    }
#pragma unroll
    for (int o = 16; o > 0; o >>= 1) s2 += __shfl_xor_sync(0xffffffffu, s2, o);
    __syncthreads();
    if (lane == 0) red[wid] = s2;
    __syncthreads();
    if (tid == 0) {
        float t = 0.f;
#pragma unroll
        for (int i = 0; i < 8; i++) t += red[i];
        red[0] = t;
    }
    __syncthreads();
    const float var  = red[0] * (1.0f / 768.0f);
    const float rstd = rsqrtf(var + 1e-5f);

#pragma unroll
    for (int i = 0; i < 3; i++) {
        int cx = tid + i * 256;
        float o = (v[i] - mean) * rstd * gamma[cx] + beta[cx];
        size_t idx = (size_t)row * EMB + cx;
        out[idx] = o;
        if (oh) oh[idx] = __float2half_rn(o);
    }
}

// ===========================================================================
// Launch
// ===========================================================================
extern "C" void kernel_launch(void* const* d_in, const int* in_sizes, int n_in,
                              void* d_out, int out_size)
{
    (void)in_sizes; (void)n_in; (void)out_size;

    const float* x   = (const float*)d_in[0];
    const float* Wq  = (const float*)d_in[1];
    const float* Wk  = (const float*)d_in[2];
    const float* Wv  = (const float*)d_in[3];
    const float* Wo  = (const float*)d_in[4];
    const float* W1  = (const float*)d_in[5];
    const float* b1  = (const float*)d_in[6];
    const float* W2  = (const float*)d_in[7];
    const float* b2  = (const float*)d_in[8];
    const float* g1  = (const float*)d_in[9];
    const float* be1 = (const float*)d_in[10];
    const float* g2  = (const float*)d_in[11];
    const float* be2 = (const float*)d_in[12];
    float* out = (float*)d_out;

    float *qkv, *tmp, *x1;
    __half *ah, *ch, *fh, *wh;
    cudaGetSymbolAddress((void**)&qkv, g_qkv);
    cudaGetSymbolAddress((void**)&tmp, g_tmp);
    cudaGetSymbolAddress((void**)&x1,  g_x1);
    cudaGetSymbolAddress((void**)&ah,  g_ah);
    cudaGetSymbolAddress((void**)&ch,  g_ch);
    cudaGetSymbolAddress((void**)&fh,  g_fh);
    cudaGetSymbolAddress((void**)&wh,  g_wh);

    const int ATTN_SMEM = (2048 + 4096 + 64 * 68 + 16384) * 4;
    cudaFuncSetAttribute(attn_kernel,
                         cudaFuncAttributeMaxDynamicSharedMemorySize, ATTN_SMEM);

    const size_t EE = (size_t)EMB * EMB;
    const size_t EF = (size_t)EMB * FFND;
    const size_t OQKV = 0, OO_ = 3 * EE, O1_ = 4 * EE, O2_ = 4 * EE + EF;

    dim3 blk(256);

    // activation conversion (x)
    cvt_kernel<<<NTOK * EMB / 2048, blk>>>(x, ah, NTOK * EMB);
    // weight conversions; Wq/Wk/Wv scatter into merged [768,2304] buffer
    cvtw_kernel<<<(int)(EE / 1024), blk>>>(Wq, wh + OQKV, EMB, QKVN, 0,    (int)EE);
    cvtw_kernel<<<(int)(EE / 1024), blk>>>(Wk, wh + OQKV, EMB, QKVN, 768,  (int)EE);
    cvtw_kernel<<<(int)(EE / 1024), blk>>>(Wv, wh + OQKV, EMB, QKVN, 1536, (int)EE);
    cvtw_kernel<<<(int)(EE / 1024), blk>>>(Wo, wh + OO_,  EMB, EMB,  0,    (int)EE);
    cvtw_kernel<<<(int)(EF / 1024), blk>>>(W1, wh + O1_,  FFND, FFND, 0,   (int)EF);
    cvtw_kernel<<<(int)(EF / 1024), blk>>>(W2, wh + O2_,  EMB,  EMB,  0,   (int)EF);

    // fused QKV projection: [NTOK,768] @ [768,2304]
    tgemm<0><<<dim3(QKVN / 128, NTOK / 128), blk>>>(
        ah, wh + OQKV, nullptr, qkv, nullptr, NTOK, QKVN, EMB);

    // attention -> ctx (fp16)
    attn_kernel<<<dim3(SEQ / 32, HEADS, BATCH), blk, ATTN_SMEM>>>(qkv, ch);

    // output projection
    tgemm<0><<<dim3(EMB / 128, NTOK / 128), blk>>>(
        ch, wh + OO_, nullptr, tmp, nullptr, NTOK, EMB, EMB);

    // residual + LN1 (emits x1 as fp16 into ah)
    add_ln_kernel<<<NTOK, blk>>>(x, tmp, g1, be1, x1, ah);

    // FFN
    tgemm<3><<<dim3(FFND / 128, NTOK / 128), blk>>>(
        ah, wh + O1_, b1, nullptr, fh, NTOK, FFND, EMB);
    tgemm<1><<<dim3(EMB / 128, NTOK / 128), blk>>>(
        fh, wh + O2_, b2, tmp, nullptr, NTOK, EMB, FFND);

    // residual + LN2
    add_ln_kernel<<<NTOK, blk>>>(x1, tmp, g2, be2, out, nullptr);
}